// round 3
// baseline (speedup 1.0000x reference)
#include <cuda_runtime.h>

// Problem constants (fixed by the reference)
#define N_NODES 100000
#define N_EDGES 50000
#define M_INC   1600000
#define D       64
#define D2      (D / 2)   // float2 chunks per row; one warp covers one row
#define BATCH   8

// ---------------------------------------------------------------------------
// Scratch (__device__ globals; allocation-free rule)
// ---------------------------------------------------------------------------
__device__ int   g_ecnt[N_EDGES];        // edge cardinality counts
__device__ int   g_eoff[N_EDGES + 1];    // CSR offsets: edge -> member nodes
__device__ int   g_ecur[N_EDGES];        // scatter cursors
__device__ int   g_ncnt[N_NODES];
__device__ int   g_noff[N_NODES + 1];    // CSR offsets: node -> incident edges
__device__ int   g_ncur[N_NODES];
__device__ int   g_emem[M_INC];          // node ids grouped by edge
__device__ int   g_nmem[M_INC];          // edge ids grouped by node
__device__ float g_ef[(long)N_EDGES * D];// edge features (stage-1 output)

// ---------------------------------------------------------------------------
// K0: zero the count arrays
// ---------------------------------------------------------------------------
__global__ void k_zero() {
    int i = blockIdx.x * blockDim.x + threadIdx.x;
    int stride = gridDim.x * blockDim.x;
    for (int j = i; j < N_EDGES; j += stride) g_ecnt[j] = 0;
    for (int j = i; j < N_NODES; j += stride) g_ncnt[j] = 0;
}

// ---------------------------------------------------------------------------
// K1: histogram both directions, 4 incidences per thread (int-only REDG)
// ---------------------------------------------------------------------------
__global__ void k_hist(const int* __restrict__ ni, const int* __restrict__ ei) {
    int t = blockIdx.x * blockDim.x + threadIdx.x;
    if (t >= M_INC / 4) return;
    int4 n4 = ((const int4*)ni)[t];
    int4 e4 = ((const int4*)ei)[t];
    atomicAdd(&g_ecnt[e4.x], 1);
    atomicAdd(&g_ecnt[e4.y], 1);
    atomicAdd(&g_ecnt[e4.z], 1);
    atomicAdd(&g_ecnt[e4.w], 1);
    atomicAdd(&g_ncnt[n4.x], 1);
    atomicAdd(&g_ncnt[n4.y], 1);
    atomicAdd(&g_ncnt[n4.z], 1);
    atomicAdd(&g_ncnt[n4.w], 1);
}

// ---------------------------------------------------------------------------
// K2: exclusive scans (block 0: edges, block 1: nodes). 1024 threads/block.
// ---------------------------------------------------------------------------
__global__ void k_scan() {
    const int* cnt; int* off; int* cur; int len;
    if (blockIdx.x == 0) { cnt = g_ecnt; off = g_eoff; cur = g_ecur; len = N_EDGES; }
    else                 { cnt = g_ncnt; off = g_noff; cur = g_ncur; len = N_NODES; }

    int t = threadIdx.x;
    int chunk = (len + 1023) >> 10;
    int beg = t * chunk;
    int end = min(beg + chunk, len);

    int s = 0;
    for (int i = beg; i < end; i++) s += cnt[i];

    __shared__ int sh[1024];
    sh[t] = s;
    __syncthreads();
    for (int d = 1; d < 1024; d <<= 1) {
        int add = (t >= d) ? sh[t - d] : 0;
        __syncthreads();
        sh[t] += add;
        __syncthreads();
    }
    int run = sh[t] - s;   // exclusive prefix of this thread's range

    for (int i = beg; i < end; i++) {
        off[i] = run;
        cur[i] = run;
        run += cnt[i];
    }
    if (beg < len && end == len) off[len] = run;
}

// ---------------------------------------------------------------------------
// K3: scatter incidences into both CSR member lists, 4 per thread.
// All 8 atomics issued before the 8 dependent stores (MLP 8).
// ---------------------------------------------------------------------------
__global__ void k_scatter(const int* __restrict__ ni, const int* __restrict__ ei) {
    int t = blockIdx.x * blockDim.x + threadIdx.x;
    if (t >= M_INC / 4) return;
    int4 n4 = ((const int4*)ni)[t];
    int4 e4 = ((const int4*)ei)[t];

    int p0 = atomicAdd(&g_ecur[e4.x], 1);
    int p1 = atomicAdd(&g_ecur[e4.y], 1);
    int p2 = atomicAdd(&g_ecur[e4.z], 1);
    int p3 = atomicAdd(&g_ecur[e4.w], 1);
    int q0 = atomicAdd(&g_ncur[n4.x], 1);
    int q1 = atomicAdd(&g_ncur[n4.y], 1);
    int q2 = atomicAdd(&g_ncur[n4.z], 1);
    int q3 = atomicAdd(&g_ncur[n4.w], 1);

    g_emem[p0] = n4.x;
    g_emem[p1] = n4.y;
    g_emem[p2] = n4.z;
    g_emem[p3] = n4.w;
    g_nmem[q0] = e4.x;
    g_nmem[q1] = e4.y;
    g_nmem[q2] = e4.z;
    g_nmem[q3] = e4.w;
}

// ---------------------------------------------------------------------------
// K4: stage 1 — warp per edge: ef[e] = (1/deg) * sum_{n in e} x[n]
// Batched loads (BATCH=8): all index loads, then all row loads, then
// predicated accumulates. Tail via address clamp + predicate.
// ---------------------------------------------------------------------------
__global__ void k_stage1(const float* __restrict__ x) {
    int warp = (blockIdx.x * blockDim.x + threadIdx.x) >> 5;
    int lane = threadIdx.x & 31;
    if (warp >= N_EDGES) return;

    int beg = g_eoff[warp];
    int end = g_eoff[warp + 1];

    const float2* x2 = (const float2*)x;
    float ax = 0.f, ay = 0.f;

    for (int base = beg; base < end; base += BATCH) {
        int idx[BATCH];
        #pragma unroll
        for (int j = 0; j < BATCH; j++)
            idx[j] = g_emem[min(base + j, end - 1)];
        float2 v[BATCH];
        #pragma unroll
        for (int j = 0; j < BATCH; j++)
            v[j] = x2[(long)idx[j] * D2 + lane];
        #pragma unroll
        for (int j = 0; j < BATCH; j++)
            if (base + j < end) { ax += v[j].x; ay += v[j].y; }
    }

    int deg = end - beg;
    float ber = (deg > 0) ? (1.0f / (float)deg) : 0.f;
    ((float2*)g_ef)[(long)warp * D2 + lane] = make_float2(ax * ber, ay * ber);
}

// ---------------------------------------------------------------------------
// K5: stage 2 — warp per node:
//   Dn[n]   = sum_{e in edges(n)} w[e]   (gathered here, no atomics)
//   out[n]  = 0.5 * (x[n] + (1/Dn) * sum_{e in edges(n)} ef[e])
// ---------------------------------------------------------------------------
__global__ void k_stage2(const float* __restrict__ x,
                         const float* __restrict__ w,
                         float* __restrict__ out) {
    int warp = (blockIdx.x * blockDim.x + threadIdx.x) >> 5;
    int lane = threadIdx.x & 31;
    if (warp >= N_NODES) return;

    int beg = g_noff[warp];
    int end = g_noff[warp + 1];

    const float2* ef2 = (const float2*)g_ef;
    float ax = 0.f, ay = 0.f, dn = 0.f;

    for (int base = beg; base < end; base += BATCH) {
        int e[BATCH];
        #pragma unroll
        for (int j = 0; j < BATCH; j++)
            e[j] = g_nmem[min(base + j, end - 1)];
        float2 v[BATCH];
        float  wv[BATCH];
        #pragma unroll
        for (int j = 0; j < BATCH; j++) {
            v[j]  = ef2[(long)e[j] * D2 + lane];
            wv[j] = __ldg(&w[e[j]]);
        }
        #pragma unroll
        for (int j = 0; j < BATCH; j++)
            if (base + j < end) { ax += v[j].x; ay += v[j].y; dn += wv[j]; }
    }

    float dnr = (dn > 0.f) ? (1.0f / dn) : 0.f;
    float2 xr = ((const float2*)x)[(long)warp * D2 + lane];
    float2 o;
    o.x = 0.5f * (xr.x + dnr * ax);
    o.y = 0.5f * (xr.y + dnr * ay);
    ((float2*)out)[(long)warp * D2 + lane] = o;
}

// ---------------------------------------------------------------------------
extern "C" void kernel_launch(void* const* d_in, const int* in_sizes, int n_in,
                              void* d_out, int out_size) {
    const float* x  = (const float*)d_in[0];
    const int*   ni = (const int*)d_in[1];
    const int*   ei = (const int*)d_in[2];
    const float* w  = (const float*)d_in[3];
    float* out = (float*)d_out;

    const int T = 256;
    const int qblocks = (M_INC / 4 + T - 1) / T;

    k_zero<<<256, T>>>();
    k_hist<<<qblocks, T>>>(ni, ei);
    k_scan<<<2, 1024>>>();
    k_scatter<<<qblocks, T>>>(ni, ei);
    k_stage1<<<(N_EDGES * 32 + T - 1) / T, T>>>(x);
    k_stage2<<<(N_NODES * 32 + T - 1) / T, T>>>(x, w, out);
}

// round 4
// speedup vs baseline: 1.7115x; 1.7115x over previous
#include <cuda_runtime.h>

// Problem constants (fixed by the reference)
#define N_NODES 100000
#define N_EDGES 50000
#define M_INC   1600000
#define D       64
#define DC      (D / 4)   // 16 float4 chunks per row
#define MH      (M_INC / 2)

// ---------------------------------------------------------------------------
// Scratch (__device__ globals; allocation-free rule)
// ---------------------------------------------------------------------------
__device__ float g_Dn[N_NODES];            // degree sum -> then 0.5/Dn
__device__ float g_Be[N_EDGES];            // cardinality -> then 1/Be
__device__ float g_ef[(long)N_EDGES * D];  // edge features

// ---------------------------------------------------------------------------
// K0: zero ef/Dn/Be and initialize out = 0.5*x (stage 2 REDGs on top of it)
// ---------------------------------------------------------------------------
__global__ void k_init(const float* __restrict__ x, float* __restrict__ out) {
    long i = blockIdx.x * (long)blockDim.x + threadIdx.x;
    long stride = (long)gridDim.x * blockDim.x;
    const long EF4 = (long)N_EDGES * DC;    // ef in float4 units
    const long XO4 = (long)N_NODES * DC;    // x/out in float4 units
    float4 z = make_float4(0.f, 0.f, 0.f, 0.f);
    for (long j = i; j < EF4; j += stride) ((float4*)g_ef)[j] = z;
    for (long j = i; j < XO4; j += stride) {
        float4 v = ((const float4*)x)[j];
        v.x *= 0.5f; v.y *= 0.5f; v.z *= 0.5f; v.w *= 0.5f;
        ((float4*)out)[j] = v;
    }
    for (long j = i; j < N_NODES; j += stride) g_Dn[j] = 0.f;
    for (long j = i; j < N_EDGES; j += stride) g_Be[j] = 0.f;
}

// ---------------------------------------------------------------------------
// K1: degrees — 4 incidences per thread, 8 float REDG
// ---------------------------------------------------------------------------
__global__ void k_degree(const int* __restrict__ ni, const int* __restrict__ ei,
                         const float* __restrict__ w) {
    int t = blockIdx.x * blockDim.x + threadIdx.x;
    if (t >= M_INC / 4) return;
    int4 n4 = ((const int4*)ni)[t];
    int4 e4 = ((const int4*)ei)[t];
    float w0 = __ldg(&w[e4.x]);
    float w1 = __ldg(&w[e4.y]);
    float w2 = __ldg(&w[e4.z]);
    float w3 = __ldg(&w[e4.w]);
    atomicAdd(&g_Be[e4.x], 1.0f);
    atomicAdd(&g_Be[e4.y], 1.0f);
    atomicAdd(&g_Be[e4.z], 1.0f);
    atomicAdd(&g_Be[e4.w], 1.0f);
    atomicAdd(&g_Dn[n4.x], w0);
    atomicAdd(&g_Dn[n4.y], w1);
    atomicAdd(&g_Dn[n4.z], w2);
    atomicAdd(&g_Dn[n4.w], w3);
}

// ---------------------------------------------------------------------------
// K2: reciprocals in place. Dn <- 0.5/Dn (folds final 0.5), Be <- 1/Be.
// ---------------------------------------------------------------------------
__global__ void k_recip() {
    int i = blockIdx.x * blockDim.x + threadIdx.x;
    if (i < N_NODES) {
        float v = g_Dn[i];
        g_Dn[i] = (v > 0.f) ? (0.5f / v) : 0.f;
    }
    if (i < N_EDGES) {
        float v = g_Be[i];
        g_Be[i] = (v > 0.f) ? (1.0f / v) : 0.f;
    }
}

// ---------------------------------------------------------------------------
// K3: stage 1 — ef[e] += Ber[e] * x[n], 2 incidences per thread (split halves)
// thread t -> chunk c = t&15, incidences m0 = t>>4 and m1 = m0 + M/2.
// ---------------------------------------------------------------------------
__global__ void k_stage1(const float* __restrict__ x,
                         const int* __restrict__ ni, const int* __restrict__ ei) {
    int t = blockIdx.x * blockDim.x + threadIdx.x;
    if (t >= MH * DC) return;
    int c  = t & 15;
    int m0 = t >> 4;
    int m1 = m0 + MH;

    int n0 = __ldg(&ni[m0]);
    int e0 = __ldg(&ei[m0]);
    int n1 = __ldg(&ni[m1]);
    int e1 = __ldg(&ei[m1]);

    float b0 = g_Be[e0];
    float b1 = g_Be[e1];

    float4 v0 = __ldg(&((const float4*)x)[(long)n0 * DC + c]);
    float4 v1 = __ldg(&((const float4*)x)[(long)n1 * DC + c]);

    v0.x *= b0; v0.y *= b0; v0.z *= b0; v0.w *= b0;
    v1.x *= b1; v1.y *= b1; v1.z *= b1; v1.w *= b1;

    float* d0 = &g_ef[(long)e0 * D + c * 4];
    float* d1 = &g_ef[(long)e1 * D + c * 4];
    asm volatile("red.global.add.v4.f32 [%0], {%1,%2,%3,%4};"
                 :: "l"(d0), "f"(v0.x), "f"(v0.y), "f"(v0.z), "f"(v0.w) : "memory");
    asm volatile("red.global.add.v4.f32 [%0], {%1,%2,%3,%4};"
                 :: "l"(d1), "f"(v1.x), "f"(v1.y), "f"(v1.z), "f"(v1.w) : "memory");
}

// ---------------------------------------------------------------------------
// K4: stage 2 — out[n] += Dnr[n] * ef[e]  (out pre-initialized to 0.5*x,
// Dnr already contains the final 0.5 factor)
// ---------------------------------------------------------------------------
__global__ void k_stage2(const int* __restrict__ ni, const int* __restrict__ ei,
                         float* __restrict__ out) {
    int t = blockIdx.x * blockDim.x + threadIdx.x;
    if (t >= MH * DC) return;
    int c  = t & 15;
    int m0 = t >> 4;
    int m1 = m0 + MH;

    int n0 = __ldg(&ni[m0]);
    int e0 = __ldg(&ei[m0]);
    int n1 = __ldg(&ni[m1]);
    int e1 = __ldg(&ei[m1]);

    float d0 = g_Dn[n0];
    float d1 = g_Dn[n1];

    float4 v0 = ((const float4*)g_ef)[(long)e0 * DC + c];
    float4 v1 = ((const float4*)g_ef)[(long)e1 * DC + c];

    v0.x *= d0; v0.y *= d0; v0.z *= d0; v0.w *= d0;
    v1.x *= d1; v1.y *= d1; v1.z *= d1; v1.w *= d1;

    float* p0 = &out[(long)n0 * D + c * 4];
    float* p1 = &out[(long)n1 * D + c * 4];
    asm volatile("red.global.add.v4.f32 [%0], {%1,%2,%3,%4};"
                 :: "l"(p0), "f"(v0.x), "f"(v0.y), "f"(v0.z), "f"(v0.w) : "memory");
    asm volatile("red.global.add.v4.f32 [%0], {%1,%2,%3,%4};"
                 :: "l"(p1), "f"(v1.x), "f"(v1.y), "f"(v1.z), "f"(v1.w) : "memory");
}

// ---------------------------------------------------------------------------
extern "C" void kernel_launch(void* const* d_in, const int* in_sizes, int n_in,
                              void* d_out, int out_size) {
    const float* x  = (const float*)d_in[0];
    const int*   ni = (const int*)d_in[1];
    const int*   ei = (const int*)d_in[2];
    const float* w  = (const float*)d_in[3];
    float* out = (float*)d_out;

    const int T = 256;

    k_init<<<2048, T>>>(x, out);
    k_degree<<<(M_INC / 4 + T - 1) / T, T>>>(ni, ei, w);
    k_recip<<<(N_NODES + T - 1) / T, T>>>();

    int stage_threads = MH * DC;                  // 12.8M threads
    k_stage1<<<(stage_threads + T - 1) / T, T>>>(x, ni, ei);
    k_stage2<<<(stage_threads + T - 1) / T, T>>>(ni, ei, out);
}

// round 6
// speedup vs baseline: 2.5636x; 1.4979x over previous
#include <cuda_runtime.h>
#include <cuda_fp16.h>

// Problem constants (fixed by the reference)
#define N_NODES 100000
#define N_EDGES 50000
#define M_INC   1600000
#define D       64
#define DCH     8          // 16B chunks per fp16 row (64 halves = 8 x uint4)
#define DC4     16         // float4 chunks per f32 row
#define MH      (M_INC / 2)

// bit-cast helpers (missing from this toolkit's headers)
__device__ __forceinline__ unsigned h2_as_u(__half2 h) {
    return *reinterpret_cast<unsigned*>(&h);
}
__device__ __forceinline__ __half2 u_as_h2(unsigned u) {
    return *reinterpret_cast<__half2*>(&u);
}

// ---------------------------------------------------------------------------
// Scratch (__device__ globals; allocation-free rule)
// ---------------------------------------------------------------------------
__device__ float  g_Dn[N_NODES];             // degree -> 0.5/Dn
__device__ float  g_Be[N_EDGES];             // cardinality -> 1/Be
__device__ __half g_xh[(long)N_NODES * D];   // x in fp16 (12.8MB)
__device__ __half g_ef[(long)N_EDGES * D];   // edge features fp16 (6.4MB)
__device__ __half g_h [(long)N_NODES * D];   // unscaled node accumulator fp16

// ---------------------------------------------------------------------------
// K0: convert x->fp16, zero ef/h/Dn/Be
// ---------------------------------------------------------------------------
__global__ void k_init(const float* __restrict__ x) {
    long i = blockIdx.x * (long)blockDim.x + threadIdx.x;
    long stride = (long)gridDim.x * blockDim.x;

    const long XH8 = (long)N_NODES * D / 8;   // 8 floats -> 8 halves per iter
    for (long j = i; j < XH8; j += stride) {
        float4 a = ((const float4*)x)[j * 2];
        float4 b = ((const float4*)x)[j * 2 + 1];
        uint4 u;
        u.x = h2_as_u(__floats2half2_rn(a.x, a.y));
        u.y = h2_as_u(__floats2half2_rn(a.z, a.w));
        u.z = h2_as_u(__floats2half2_rn(b.x, b.y));
        u.w = h2_as_u(__floats2half2_rn(b.z, b.w));
        ((uint4*)g_xh)[j] = u;
    }

    const long EF8 = (long)N_EDGES * D / 8;
    const long H8  = (long)N_NODES * D / 8;
    uint4 z = make_uint4(0u, 0u, 0u, 0u);
    for (long j = i; j < EF8; j += stride) ((uint4*)g_ef)[j] = z;
    for (long j = i; j < H8;  j += stride) ((uint4*)g_h)[j]  = z;
    for (long j = i; j < N_NODES; j += stride) g_Dn[j] = 0.f;
    for (long j = i; j < N_EDGES; j += stride) g_Be[j] = 0.f;
}

// ---------------------------------------------------------------------------
// K1: degrees — 4 incidences per thread, 8 float REDG
// ---------------------------------------------------------------------------
__global__ void k_degree(const int* __restrict__ ni, const int* __restrict__ ei,
                         const float* __restrict__ w) {
    int t = blockIdx.x * blockDim.x + threadIdx.x;
    if (t >= M_INC / 4) return;
    int4 n4 = ((const int4*)ni)[t];
    int4 e4 = ((const int4*)ei)[t];
    float w0 = __ldg(&w[e4.x]);
    float w1 = __ldg(&w[e4.y]);
    float w2 = __ldg(&w[e4.z]);
    float w3 = __ldg(&w[e4.w]);
    atomicAdd(&g_Be[e4.x], 1.0f);
    atomicAdd(&g_Be[e4.y], 1.0f);
    atomicAdd(&g_Be[e4.z], 1.0f);
    atomicAdd(&g_Be[e4.w], 1.0f);
    atomicAdd(&g_Dn[n4.x], w0);
    atomicAdd(&g_Dn[n4.y], w1);
    atomicAdd(&g_Dn[n4.z], w2);
    atomicAdd(&g_Dn[n4.w], w3);
}

// ---------------------------------------------------------------------------
// K2: reciprocals in place. Dn <- 0.5/Dn (folds final 0.5), Be <- 1/Be.
// ---------------------------------------------------------------------------
__global__ void k_recip() {
    int i = blockIdx.x * blockDim.x + threadIdx.x;
    if (i < N_NODES) {
        float v = g_Dn[i];
        g_Dn[i] = (v > 0.f) ? (0.5f / v) : 0.f;
    }
    if (i < N_EDGES) {
        float v = g_Be[i];
        g_Be[i] = (v > 0.f) ? (1.0f / v) : 0.f;
    }
}

// ---------------------------------------------------------------------------
// K3: stage 1 — ef[e] += Ber[e] * xh[n]  (fp16x2 vector REDG)
// thread t -> chunk c = t&7 (16B), incidences m0 = t>>3 and m1 = m0 + M/2.
// ---------------------------------------------------------------------------
__global__ void k_stage1(const int* __restrict__ ni, const int* __restrict__ ei) {
    int t = blockIdx.x * blockDim.x + threadIdx.x;
    if (t >= MH * DCH) return;
    int c  = t & 7;
    int m0 = t >> 3;
    int m1 = m0 + MH;

    int n0 = __ldg(&ni[m0]);
    int e0 = __ldg(&ei[m0]);
    int n1 = __ldg(&ni[m1]);
    int e1 = __ldg(&ei[m1]);

    __half2 b0 = __float2half2_rn(g_Be[e0]);
    __half2 b1 = __float2half2_rn(g_Be[e1]);

    uint4 u0 = __ldg(&((const uint4*)g_xh)[(long)n0 * DCH + c]);
    uint4 u1 = __ldg(&((const uint4*)g_xh)[(long)n1 * DCH + c]);

    uint4 s0, s1;
    s0.x = h2_as_u(__hmul2(u_as_h2(u0.x), b0));
    s0.y = h2_as_u(__hmul2(u_as_h2(u0.y), b0));
    s0.z = h2_as_u(__hmul2(u_as_h2(u0.z), b0));
    s0.w = h2_as_u(__hmul2(u_as_h2(u0.w), b0));
    s1.x = h2_as_u(__hmul2(u_as_h2(u1.x), b1));
    s1.y = h2_as_u(__hmul2(u_as_h2(u1.y), b1));
    s1.z = h2_as_u(__hmul2(u_as_h2(u1.z), b1));
    s1.w = h2_as_u(__hmul2(u_as_h2(u1.w), b1));

    __half* d0 = &g_ef[(long)e0 * D + c * 8];
    __half* d1 = &g_ef[(long)e1 * D + c * 8];
    asm volatile("red.global.add.noftz.v4.f16x2 [%0], {%1,%2,%3,%4};"
                 :: "l"(d0), "r"(s0.x), "r"(s0.y), "r"(s0.z), "r"(s0.w) : "memory");
    asm volatile("red.global.add.noftz.v4.f16x2 [%0], {%1,%2,%3,%4};"
                 :: "l"(d1), "r"(s1.x), "r"(s1.y), "r"(s1.z), "r"(s1.w) : "memory");
}

// ---------------------------------------------------------------------------
// K4: stage 2 — h[n] += ef[e]  (pure fp16 scatter, no scaling)
// ---------------------------------------------------------------------------
__global__ void k_stage2(const int* __restrict__ ni, const int* __restrict__ ei) {
    int t = blockIdx.x * blockDim.x + threadIdx.x;
    if (t >= MH * DCH) return;
    int c  = t & 7;
    int m0 = t >> 3;
    int m1 = m0 + MH;

    int n0 = __ldg(&ni[m0]);
    int e0 = __ldg(&ei[m0]);
    int n1 = __ldg(&ni[m1]);
    int e1 = __ldg(&ei[m1]);

    uint4 u0 = ((const uint4*)g_ef)[(long)e0 * DCH + c];
    uint4 u1 = ((const uint4*)g_ef)[(long)e1 * DCH + c];

    __half* d0 = &g_h[(long)n0 * D + c * 8];
    __half* d1 = &g_h[(long)n1 * D + c * 8];
    asm volatile("red.global.add.noftz.v4.f16x2 [%0], {%1,%2,%3,%4};"
                 :: "l"(d0), "r"(u0.x), "r"(u0.y), "r"(u0.z), "r"(u0.w) : "memory");
    asm volatile("red.global.add.noftz.v4.f16x2 [%0], {%1,%2,%3,%4};"
                 :: "l"(d1), "r"(u1.x), "r"(u1.y), "r"(u1.z), "r"(u1.w) : "memory");
}

// ---------------------------------------------------------------------------
// K5: final — out = 0.5*x + (0.5/Dn)*h   (g_Dn already holds 0.5/Dn)
// thread per float4 chunk (4 floats / 4 halves)
// ---------------------------------------------------------------------------
__global__ void k_final(const float* __restrict__ x, float* __restrict__ out) {
    int t = blockIdx.x * blockDim.x + threadIdx.x;
    if (t >= N_NODES * DC4) return;
    int node = t >> 4;
    float dn = g_Dn[node];

    float4 xv = ((const float4*)x)[t];
    uint2 hu = ((const uint2*)g_h)[t];
    float2 h01 = __half22float2(u_as_h2(hu.x));
    float2 h23 = __half22float2(u_as_h2(hu.y));

    float4 o;
    o.x = 0.5f * xv.x + dn * h01.x;
    o.y = 0.5f * xv.y + dn * h01.y;
    o.z = 0.5f * xv.z + dn * h23.x;
    o.w = 0.5f * xv.w + dn * h23.y;
    ((float4*)out)[t] = o;
}

// ---------------------------------------------------------------------------
extern "C" void kernel_launch(void* const* d_in, const int* in_sizes, int n_in,
                              void* d_out, int out_size) {
    const float* x  = (const float*)d_in[0];
    const int*   ni = (const int*)d_in[1];
    const int*   ei = (const int*)d_in[2];
    const float* w  = (const float*)d_in[3];
    float* out = (float*)d_out;

    const int T = 256;

    k_init<<<2048, T>>>(x);
    k_degree<<<(M_INC / 4 + T - 1) / T, T>>>(ni, ei, w);
    k_recip<<<(N_NODES + T - 1) / T, T>>>();

    int stage_threads = MH * DCH;                 // 6.4M threads
    k_stage1<<<(stage_threads + T - 1) / T, T>>>(ni, ei);
    k_stage2<<<(stage_threads + T - 1) / T, T>>>(ni, ei);

    k_final<<<(N_NODES * DC4 + T - 1) / T, T>>>(x, out);
}

// round 7
// speedup vs baseline: 2.7321x; 1.0658x over previous
#include <cuda_runtime.h>
#include <cuda_fp16.h>

// Problem constants (fixed by the reference)
#define N_NODES 100000
#define N_EDGES 50000
#define M_INC   1600000
#define D       64
#define DCH     8          // 16B chunks per fp16 row (64 halves = 8 x uint4)
#define DC4     16         // float4 chunks per f32 row
#define MH      (M_INC / 2)

// bit-cast helpers
__device__ __forceinline__ unsigned h2_as_u(__half2 h) {
    return *reinterpret_cast<unsigned*>(&h);
}
__device__ __forceinline__ __half2 u_as_h2(unsigned u) {
    return *reinterpret_cast<__half2*>(&u);
}

// ---------------------------------------------------------------------------
// Scratch (__device__ globals; allocation-free rule)
// ---------------------------------------------------------------------------
__device__ float  g_Dn[N_NODES];             // weighted node degree (raw)
__device__ float  g_Be[N_EDGES];             // edge cardinality (raw count)
__device__ __half g_xh[(long)N_NODES * D];   // x in fp16
__device__ __half g_ef[(long)N_EDGES * D];   // edge features fp16
__device__ __half g_h [(long)N_NODES * D];   // unscaled node accumulator fp16

// ---------------------------------------------------------------------------
// K0: convert x->fp16, zero ef/h/Dn/Be
// ---------------------------------------------------------------------------
__global__ void k_init(const float* __restrict__ x) {
    long i = blockIdx.x * (long)blockDim.x + threadIdx.x;
    long stride = (long)gridDim.x * blockDim.x;

    const long XH8 = (long)N_NODES * D / 8;
    for (long j = i; j < XH8; j += stride) {
        float4 a = ((const float4*)x)[j * 2];
        float4 b = ((const float4*)x)[j * 2 + 1];
        uint4 u;
        u.x = h2_as_u(__floats2half2_rn(a.x, a.y));
        u.y = h2_as_u(__floats2half2_rn(a.z, a.w));
        u.z = h2_as_u(__floats2half2_rn(b.x, b.y));
        u.w = h2_as_u(__floats2half2_rn(b.z, b.w));
        ((uint4*)g_xh)[j] = u;
    }

    const long EF8 = (long)N_EDGES * D / 8;
    const long H8  = (long)N_NODES * D / 8;
    uint4 z = make_uint4(0u, 0u, 0u, 0u);
    for (long j = i; j < EF8; j += stride) ((uint4*)g_ef)[j] = z;
    for (long j = i; j < H8;  j += stride) ((uint4*)g_h)[j]  = z;
    for (long j = i; j < N_NODES; j += stride) g_Dn[j] = 0.f;
    for (long j = i; j < N_EDGES; j += stride) g_Be[j] = 0.f;
}

// ---------------------------------------------------------------------------
// K1: stage 1 — ef[e] += xh[n] (raw, fp16x2 vector REDG);
//     lane c==0 also counts edge cardinality into g_Be.
// thread t -> chunk c = t&7 (16B), incidences m0 = t>>3 and m1 = m0 + M/2.
// ---------------------------------------------------------------------------
__global__ void k_stage1(const int* __restrict__ ni, const int* __restrict__ ei) {
    int t = blockIdx.x * blockDim.x + threadIdx.x;
    if (t >= MH * DCH) return;
    int c  = t & 7;
    int m0 = t >> 3;
    int m1 = m0 + MH;

    int n0 = __ldg(&ni[m0]);
    int e0 = __ldg(&ei[m0]);
    int n1 = __ldg(&ni[m1]);
    int e1 = __ldg(&ei[m1]);

    uint4 u0 = __ldg(&((const uint4*)g_xh)[(long)n0 * DCH + c]);
    uint4 u1 = __ldg(&((const uint4*)g_xh)[(long)n1 * DCH + c]);

    __half* d0 = &g_ef[(long)e0 * D + c * 8];
    __half* d1 = &g_ef[(long)e1 * D + c * 8];
    asm volatile("red.global.add.noftz.v4.f16x2 [%0], {%1,%2,%3,%4};"
                 :: "l"(d0), "r"(u0.x), "r"(u0.y), "r"(u0.z), "r"(u0.w) : "memory");
    asm volatile("red.global.add.noftz.v4.f16x2 [%0], {%1,%2,%3,%4};"
                 :: "l"(d1), "r"(u1.x), "r"(u1.y), "r"(u1.z), "r"(u1.w) : "memory");

    if (c == 0) {
        atomicAdd(&g_Be[e0], 1.0f);
        atomicAdd(&g_Be[e1], 1.0f);
    }
}

// ---------------------------------------------------------------------------
// K2: scale ef rows by 1/Be (safe recip). One uint4 chunk per thread.
// ---------------------------------------------------------------------------
__global__ void k_scale_ef() {
    int t = blockIdx.x * blockDim.x + threadIdx.x;
    if (t >= N_EDGES * DCH) return;
    int e = t >> 3;
    float b = g_Be[e];
    float br = (b > 0.f) ? (1.0f / b) : 0.f;
    __half2 bh = __float2half2_rn(br);

    uint4 u = ((const uint4*)g_ef)[t];
    u.x = h2_as_u(__hmul2(u_as_h2(u.x), bh));
    u.y = h2_as_u(__hmul2(u_as_h2(u.y), bh));
    u.z = h2_as_u(__hmul2(u_as_h2(u.z), bh));
    u.w = h2_as_u(__hmul2(u_as_h2(u.w), bh));
    ((uint4*)g_ef)[t] = u;
}

// ---------------------------------------------------------------------------
// K3: stage 2 — h[n] += ef[e] (fp16 scatter);
//     lane c==0 also accumulates Dn[n] += w[e].
// ---------------------------------------------------------------------------
__global__ void k_stage2(const int* __restrict__ ni, const int* __restrict__ ei,
                         const float* __restrict__ w) {
    int t = blockIdx.x * blockDim.x + threadIdx.x;
    if (t >= MH * DCH) return;
    int c  = t & 7;
    int m0 = t >> 3;
    int m1 = m0 + MH;

    int n0 = __ldg(&ni[m0]);
    int e0 = __ldg(&ei[m0]);
    int n1 = __ldg(&ni[m1]);
    int e1 = __ldg(&ei[m1]);

    uint4 u0 = ((const uint4*)g_ef)[(long)e0 * DCH + c];
    uint4 u1 = ((const uint4*)g_ef)[(long)e1 * DCH + c];

    __half* d0 = &g_h[(long)n0 * D + c * 8];
    __half* d1 = &g_h[(long)n1 * D + c * 8];
    asm volatile("red.global.add.noftz.v4.f16x2 [%0], {%1,%2,%3,%4};"
                 :: "l"(d0), "r"(u0.x), "r"(u0.y), "r"(u0.z), "r"(u0.w) : "memory");
    asm volatile("red.global.add.noftz.v4.f16x2 [%0], {%1,%2,%3,%4};"
                 :: "l"(d1), "r"(u1.x), "r"(u1.y), "r"(u1.z), "r"(u1.w) : "memory");

    if (c == 0) {
        atomicAdd(&g_Dn[n0], __ldg(&w[e0]));
        atomicAdd(&g_Dn[n1], __ldg(&w[e1]));
    }
}

// ---------------------------------------------------------------------------
// K4: final — out = 0.5*x + (0.5/Dn)*h  (safe recip inline)
// ---------------------------------------------------------------------------
__global__ void k_final(const float* __restrict__ x, float* __restrict__ out) {
    int t = blockIdx.x * blockDim.x + threadIdx.x;
    if (t >= N_NODES * DC4) return;
    int node = t >> 4;
    float dnv = g_Dn[node];
    float dn = (dnv > 0.f) ? (0.5f / dnv) : 0.f;

    float4 xv = ((const float4*)x)[t];
    uint2 hu = ((const uint2*)g_h)[t];
    float2 h01 = __half22float2(u_as_h2(hu.x));
    float2 h23 = __half22float2(u_as_h2(hu.y));

    float4 o;
    o.x = 0.5f * xv.x + dn * h01.x;
    o.y = 0.5f * xv.y + dn * h01.y;
    o.z = 0.5f * xv.z + dn * h23.x;
    o.w = 0.5f * xv.w + dn * h23.y;
    ((float4*)out)[t] = o;
}

// ---------------------------------------------------------------------------
extern "C" void kernel_launch(void* const* d_in, const int* in_sizes, int n_in,
                              void* d_out, int out_size) {
    const float* x  = (const float*)d_in[0];
    const int*   ni = (const int*)d_in[1];
    const int*   ei = (const int*)d_in[2];
    const float* w  = (const float*)d_in[3];
    float* out = (float*)d_out;

    const int T = 256;
    int stage_threads = MH * DCH;                 // 6.4M threads

    k_init<<<2048, T>>>(x);
    k_stage1<<<(stage_threads + T - 1) / T, T>>>(ni, ei);
    k_scale_ef<<<(N_EDGES * DCH + T - 1) / T, T>>>();
    k_stage2<<<(stage_threads + T - 1) / T, T>>>(ni, ei, w);
    k_final<<<(N_NODES * DC4 + T - 1) / T, T>>>(x, out);
}